// round 1
// baseline (speedup 1.0000x reference)
#include <cuda_runtime.h>
#include <math.h>
#include <float.h>

#define NB   32
#define NM   10000
#define ND   512
#define KTOP 5
#define RV   32768            // 32*32*32 voxels per memory slot

#define BN   64               // m-tile per block
#define KC   64               // k-chunk
#define KPAD 68               // padded row (float4-aligned, limits conflicts to 4-way)

// ---- device scratch (no allocations allowed) ----
__device__ float g_sim[NB * NM];      // sim[b][m]
__device__ float g_invx[NB];
__device__ int   g_topidx[NB * KTOP];
__device__ float g_topval[NB * KTOP];

// ---------------- kernel 0: 1/||x_b|| ----------------
__global__ void xnorm_kernel(const float* __restrict__ x) {
    int b    = threadIdx.x >> 5;      // 32 warps, one per batch row
    int lane = threadIdx.x & 31;
    const float4* x4 = reinterpret_cast<const float4*>(x) + b * (ND / 4);
    float s = 0.f;
#pragma unroll
    for (int j = 0; j < 4; ++j) {
        float4 v = x4[j * 32 + lane];
        s += v.x * v.x + v.y * v.y + v.z * v.z + v.w * v.w;
    }
#pragma unroll
    for (int o = 16; o > 0; o >>= 1) s += __shfl_xor_sync(0xffffffffu, s, o);
    if (lane == 0) g_invx[b] = 1.f / fmaxf(sqrtf(s), 1e-12f);
}

// ---------------- kernel 1: sim = qn @ knT ----------------
// C[32 x 10000] = X[32 x 512] * K^T, normalized by row norms.
// Block: 128 threads, tile 32(b) x 64(m); thread tile 4b x 4m.
__global__ __launch_bounds__(128) void sim_kernel(const float* __restrict__ x,
                                                  const float* __restrict__ keys) {
    __shared__ float xs[NB * KPAD];   // x chunk  [b][kpad]
    __shared__ float ks[BN * KPAD];   // key chunk[mm][kpad]

    const int tid = threadIdx.x;
    const int m0  = blockIdx.x * BN;
    const int b_t = tid & 7;          // 8 b-groups of 4
    const int m_t = tid >> 3;         // 16 m-groups of 4

    float acc[4][4] = {};
    float ksq[4]    = {};

    for (int c = 0; c < ND / KC; ++c) {
        const int k0 = c * KC;
        // fill x chunk: 32 rows x 16 float4 (coalesced)
        {
            const float4* xg = reinterpret_cast<const float4*>(x);
#pragma unroll
            for (int t = 0; t < 4; ++t) {
                int idx = tid + t * 128;            // 0..511
                int row = idx >> 4;
                int c4  = idx & 15;
                float4 v = xg[row * (ND / 4) + (k0 >> 2) + c4];
                *reinterpret_cast<float4*>(xs + row * KPAD + c4 * 4) = v;
            }
        }
        // fill key chunk: 64 rows x 16 float4 (coalesced, zero-pad past NM)
        {
            const float4* kg = reinterpret_cast<const float4*>(keys);
#pragma unroll
            for (int t = 0; t < 8; ++t) {
                int idx = tid + t * 128;            // 0..1023
                int row = idx >> 4;
                int c4  = idx & 15;
                int gm  = m0 + row;
                float4 v = make_float4(0.f, 0.f, 0.f, 0.f);
                if (gm < NM) v = kg[gm * (ND / 4) + (k0 >> 2) + c4];
                *reinterpret_cast<float4*>(ks + row * KPAD + c4 * 4) = v;
            }
        }
        __syncthreads();

#pragma unroll 4
        for (int kk = 0; kk < KC / 4; ++kk) {
            float4 xa[4], ka[4];
#pragma unroll
            for (int i = 0; i < 4; ++i)
                xa[i] = *reinterpret_cast<const float4*>(xs + (b_t * 4 + i) * KPAD + kk * 4);
#pragma unroll
            for (int j = 0; j < 4; ++j) {
                ka[j] = *reinterpret_cast<const float4*>(ks + (m_t * 4 + j) * KPAD + kk * 4);
                ksq[j] += ka[j].x * ka[j].x + ka[j].y * ka[j].y
                        + ka[j].z * ka[j].z + ka[j].w * ka[j].w;
            }
#pragma unroll
            for (int i = 0; i < 4; ++i)
#pragma unroll
                for (int j = 0; j < 4; ++j)
                    acc[i][j] += xa[i].x * ka[j].x + xa[i].y * ka[j].y
                               + xa[i].z * ka[j].z + xa[i].w * ka[j].w;
        }
        __syncthreads();
    }

    float invx[4];
#pragma unroll
    for (int i = 0; i < 4; ++i) invx[i] = g_invx[b_t * 4 + i];
    float invk[4];
#pragma unroll
    for (int j = 0; j < 4; ++j) invk[j] = 1.f / fmaxf(sqrtf(ksq[j]), 1e-12f);

#pragma unroll
    for (int i = 0; i < 4; ++i) {
        int b = b_t * 4 + i;
#pragma unroll
        for (int j = 0; j < 4; ++j) {
            int gm = m0 + m_t * 4 + j;
            if (gm < NM) g_sim[b * NM + gm] = acc[i][j] * invx[i] * invk[j];
        }
    }
}

// ---------------- kernel 2: top-5 per batch row ----------------
// One block per b. Row cached in shared; 5 rounds of argmax with masking.
// Tie-break matches jax.lax.top_k: equal value -> lower index first.
__global__ __launch_bounds__(256) void topk_kernel() {
    __shared__ float sv[256];
    __shared__ int   si[256];
    extern __shared__ float vals[];   // NM floats (40 KB)

    const int b   = blockIdx.x;
    const int tid = threadIdx.x;

    for (int i = tid; i < NM; i += 256) vals[i] = g_sim[b * NM + i];
    __syncthreads();

    for (int k = 0; k < KTOP; ++k) {
        float bv = -FLT_MAX;
        int   bi = NM;
        for (int i = tid; i < NM; i += 256) {
            float v = vals[i];
            if (v > bv || (v == bv && i < bi)) { bv = v; bi = i; }
        }
        sv[tid] = bv; si[tid] = bi;
        __syncthreads();
        for (int s = 128; s > 0; s >>= 1) {
            if (tid < s) {
                float v2 = sv[tid + s]; int i2 = si[tid + s];
                if (v2 > sv[tid] || (v2 == sv[tid] && i2 < si[tid])) {
                    sv[tid] = v2; si[tid] = i2;
                }
            }
            __syncthreads();
        }
        if (tid == 0) {
            g_topidx[b * KTOP + k] = si[0];
            g_topval[b * KTOP + k] = sv[0];
            vals[si[0]] = -FLT_MAX;   // mask winner for next round
        }
        __syncthreads();
    }
}

// ---------------- kernel 3: gather voxel grids + tails ----------------
__global__ __launch_bounds__(256) void gather_kernel(const float* __restrict__ mv,
                                                     float* __restrict__ out,
                                                     long long out_size) {
    const int p   = blockIdx.x;                 // b*KTOP + k
    const int idx = g_topidx[p];
    const float4* src = reinterpret_cast<const float4*>(mv + (long long)idx * RV);
    float4*       dst = reinterpret_cast<float4*>(out + (long long)p * RV);
#pragma unroll 8
    for (int i = threadIdx.x; i < RV / 4; i += 256) dst[i] = src[i];

    if (threadIdx.x == 0) {
        const long long base = (long long)NB * KTOP * RV;
        if (out_size >= base + 2LL * NB * KTOP) {
            out[base + p]             = (float)g_topidx[p];   // top_idx section
            out[base + NB * KTOP + p] = g_topval[p];          // top_vals section
        }
    }
}

extern "C" void kernel_launch(void* const* d_in, const int* in_sizes, int n_in,
                              void* d_out, int out_size) {
    const float* x    = (const float*)d_in[0];
    const float* keys = (const float*)d_in[1];
    const float* mv   = (const float*)d_in[2];
    // d_in[3] = top_k scalar; fixed at 5 for this problem.
    float* out = (float*)d_out;

    xnorm_kernel<<<1, 1024>>>(x);
    sim_kernel<<<(NM + BN - 1) / BN, 128>>>(x, keys);
    topk_kernel<<<NB, 256, NM * (int)sizeof(float)>>>();
    gather_kernel<<<NB * KTOP, 256>>>(mv, out, (long long)out_size);
}

// round 2
// speedup vs baseline: 1.3894x; 1.3894x over previous
#include <cuda_runtime.h>
#include <math.h>
#include <float.h>
#include <limits.h>

#define NB   32
#define NM   10000
#define ND   512
#define KTOP 5
#define RV   32768            // 32*32*32 voxels per memory slot

#define BN   64               // m-tile per block
#define KC   64               // k-chunk
#define KPX  68               // xs row pad (float4-aligned)
#define KPK  67               // ks row pad (odd -> scalar loads spread banks)

// ---- device scratch ----
__device__ float g_sim[NB * NM];
__device__ float g_invx[NB];
__device__ int   g_topidx[NB * KTOP];
__device__ float g_topval[NB * KTOP];

// ---------------- kernel 0: 1/||x_b|| ----------------
__global__ void xnorm_kernel(const float* __restrict__ x) {
    int b    = threadIdx.x >> 5;
    int lane = threadIdx.x & 31;
    const float4* x4 = reinterpret_cast<const float4*>(x) + b * (ND / 4);
    float s = 0.f;
#pragma unroll
    for (int j = 0; j < 4; ++j) {
        float4 v = x4[j * 32 + lane];
        s += v.x * v.x + v.y * v.y + v.z * v.z + v.w * v.w;
    }
#pragma unroll
    for (int o = 16; o > 0; o >>= 1) s += __shfl_xor_sync(0xffffffffu, s, o);
    if (lane == 0) g_invx[b] = 1.f / fmaxf(sqrtf(s), 1e-12f);
}

// ---------------- kernel 1: sim ----------------
// Block: 64 threads. Tile: 8 b-rows x 64 m-cols. Thread: 2b x 4m.
// Grid: (157 m-tiles, 4 b-tiles) = 628 blocks (balance 1.18 on 148 SMs).
__global__ __launch_bounds__(64) void sim_kernel(const float* __restrict__ x,
                                                 const float* __restrict__ keys) {
    __shared__ float xs[8 * KPX];
    __shared__ float ks[BN * KPK];
    __shared__ float ksqs[BN];

    const int tid = threadIdx.x;
    const int m0  = blockIdx.x * BN;
    const int b0  = blockIdx.y * 8;
    const int m_t = tid & 15;          // 16 m-groups of 4 (consecutive)
    const int b_t = tid >> 4;          // 4 b-groups of 2 (consecutive)

    float acc[2][4] = {};
    float kq = 0.f;

    for (int c = 0; c < ND / KC; ++c) {
        const int k0 = c * KC;
        // x chunk: 8 rows x 16 float4 = 128 float4, 2 per thread
        {
            const float4* xg = reinterpret_cast<const float4*>(x);
#pragma unroll
            for (int t = 0; t < 2; ++t) {
                int idx = tid + t * 64;
                int row = idx >> 4, c4 = idx & 15;
                float4 v = xg[(b0 + row) * (ND / 4) + (k0 >> 2) + c4];
                *reinterpret_cast<float4*>(xs + row * KPX + c4 * 4) = v;
            }
        }
        // key chunk: 64 rows x 16 float4 = 1024 float4, 16 per thread
        {
            const float4* kg = reinterpret_cast<const float4*>(keys);
#pragma unroll
            for (int t = 0; t < 16; ++t) {
                int idx = tid + t * 64;
                int row = idx >> 4, c4 = idx & 15;
                int gm  = m0 + row;
                float4 v = make_float4(0.f, 0.f, 0.f, 0.f);
                if (gm < NM) v = kg[gm * (ND / 4) + (k0 >> 2) + c4];
                float* d = ks + row * KPK + c4 * 4;   // KPK odd -> scalar STS
                d[0] = v.x; d[1] = v.y; d[2] = v.z; d[3] = v.w;
            }
        }
        __syncthreads();

        // key-norm partial: thread tid owns m-row tid (conflict-free: 67 coprime 32)
        {
            const float* kr = ks + tid * KPK;
#pragma unroll 8
            for (int k = 0; k < KC; ++k) { float v = kr[k]; kq += v * v; }
        }

        // main FMA loop
#pragma unroll 4
        for (int kk = 0; kk < KC / 4; ++kk) {
            float4 xa0 = *reinterpret_cast<const float4*>(xs + (b_t * 2 + 0) * KPX + kk * 4);
            float4 xa1 = *reinterpret_cast<const float4*>(xs + (b_t * 2 + 1) * KPX + kk * 4);
#pragma unroll
            for (int j = 0; j < 4; ++j) {
                const float* kr = ks + (m_t * 4 + j) * KPK + kk * 4;
                float kv0 = kr[0], kv1 = kr[1], kv2 = kr[2], kv3 = kr[3];
                acc[0][j] += xa0.x * kv0 + xa0.y * kv1 + xa0.z * kv2 + xa0.w * kv3;
                acc[1][j] += xa1.x * kv0 + xa1.y * kv1 + xa1.z * kv2 + xa1.w * kv3;
            }
        }
        __syncthreads();
    }

    ksqs[tid] = kq;
    __syncthreads();

    const float invx0 = g_invx[b0 + b_t * 2 + 0];
    const float invx1 = g_invx[b0 + b_t * 2 + 1];
#pragma unroll
    for (int j = 0; j < 4; ++j) {
        int gm = m0 + m_t * 4 + j;
        if (gm < NM) {
            float invk = 1.f / fmaxf(sqrtf(ksqs[m_t * 4 + j]), 1e-12f);
            g_sim[(b0 + b_t * 2 + 0) * NM + gm] = acc[0][j] * invx0 * invk;
            g_sim[(b0 + b_t * 2 + 1) * NM + gm] = acc[1][j] * invx1 * invk;
        }
    }
}

// ---------------- kernel 2: top-5 per batch row ----------------
// Per-thread register top-5 over strided scan, then 5 argmax rounds over the
// 1280-candidate pool. Tie-break matches jax.lax.top_k (equal -> lower index).
__global__ __launch_bounds__(256) void topk_kernel(float* __restrict__ out,
                                                   long long out_size) {
    __shared__ float sv[256 * KTOP];
    __shared__ int   si[256 * KTOP];
    __shared__ float wv[8];
    __shared__ int   wi[8];
    __shared__ int   wp[8];

    const int b = blockIdx.x, tid = threadIdx.x;
    const int lane = tid & 31, warp = tid >> 5;

    float v[KTOP]; int ix[KTOP];
#pragma unroll
    for (int p = 0; p < KTOP; ++p) { v[p] = -FLT_MAX; ix[p] = INT_MAX; }

    const float* row = g_sim + b * NM;
    for (int i = tid; i < NM; i += 256) {
        float val = row[i];
        if (val > v[KTOP - 1]) {                 // ascending i -> ties keep lower idx
            v[KTOP - 1] = val; ix[KTOP - 1] = i;
#pragma unroll
            for (int q = KTOP - 1; q > 0; --q) {
                if (v[q] > v[q - 1]) {
                    float tv = v[q]; v[q] = v[q - 1]; v[q - 1] = tv;
                    int   ti = ix[q]; ix[q] = ix[q - 1]; ix[q - 1] = ti;
                }
            }
        }
    }
#pragma unroll
    for (int p = 0; p < KTOP; ++p) { sv[p * 256 + tid] = v[p]; si[p * 256 + tid] = ix[p]; }
    __syncthreads();

    for (int k = 0; k < KTOP; ++k) {
        float bv = -FLT_MAX; int bi = INT_MAX; int bp = -1;
#pragma unroll
        for (int t = 0; t < KTOP; ++t) {
            int j = t * 256 + tid;
            float vv = sv[j]; int ii = si[j];
            if (vv > bv || (vv == bv && ii < bi)) { bv = vv; bi = ii; bp = j; }
        }
#pragma unroll
        for (int o = 16; o > 0; o >>= 1) {
            float ov = __shfl_down_sync(0xffffffffu, bv, o);
            int   oi = __shfl_down_sync(0xffffffffu, bi, o);
            int   op = __shfl_down_sync(0xffffffffu, bp, o);
            if (ov > bv || (ov == bv && oi < bi)) { bv = ov; bi = oi; bp = op; }
        }
        if (lane == 0) { wv[warp] = bv; wi[warp] = bi; wp[warp] = bp; }
        __syncthreads();
        if (tid == 0) {
            float fv = wv[0]; int fi = wi[0]; int fp = wp[0];
#pragma unroll
            for (int w = 1; w < 8; ++w) {
                if (wv[w] > fv || (wv[w] == fv && wi[w] < fi)) {
                    fv = wv[w]; fi = wi[w]; fp = wp[w];
                }
            }
            g_topidx[b * KTOP + k] = fi;
            g_topval[b * KTOP + k] = fv;
            sv[fp] = -FLT_MAX;                   // mask winner
            const long long base = (long long)NB * KTOP * RV;
            if (out_size >= base + 2LL * NB * KTOP) {
                out[base + b * KTOP + k]             = (float)fi;
                out[base + NB * KTOP + b * KTOP + k] = fv;
            }
        }
        __syncthreads();
    }
}

// ---------------- kernel 3: gather (8 blocks per slot) ----------------
__global__ __launch_bounds__(256) void gather_kernel(const float* __restrict__ mv,
                                                     float* __restrict__ out) {
    const int p    = blockIdx.x >> 3;           // slot pair (b*KTOP+k)
    const int part = blockIdx.x & 7;            // 1/8 of the voxel grid
    const int idx  = g_topidx[p];
    const float4* src = reinterpret_cast<const float4*>(mv + (long long)idx * RV) + part * 1024;
    float4*       dst = reinterpret_cast<float4*>(out + (long long)p * RV) + part * 1024;
#pragma unroll
    for (int j = 0; j < 4; ++j) dst[threadIdx.x + j * 256] = src[threadIdx.x + j * 256];
}

extern "C" void kernel_launch(void* const* d_in, const int* in_sizes, int n_in,
                              void* d_out, int out_size) {
    const float* x    = (const float*)d_in[0];
    const float* keys = (const float*)d_in[1];
    const float* mv   = (const float*)d_in[2];
    float* out = (float*)d_out;

    xnorm_kernel<<<1, 1024>>>(x);
    dim3 simgrid((NM + BN - 1) / BN, 4);
    sim_kernel<<<simgrid, 64>>>(x, keys);
    topk_kernel<<<NB, 256>>>(out, (long long)out_size);
    gather_kernel<<<NB * KTOP * 8, 256>>>(mv, out);
}